// round 3
// baseline (speedup 1.0000x reference)
#include <cuda_runtime.h>
#include <cuda_bf16.h>
#include <cstdint>
#include <cstddef>

typedef unsigned long long ull;

#define B_  64
#define S_  200
#define T_  199
#define H_  256
#define G4  1024
#define NI_ 50000

#define NCC 32          // column chunks: each owns 8 h-elems x 4 gates = 32 gate rows
#define NBG 4           // independent batch groups of 16
#define K1_BLOCKS 1592  // 1592*8 warps = 199*64 (b,t) pairs exactly

// ------------------------- device scratch (no allocs allowed) ---------------
__device__ __align__(16) float g_xp[(size_t)T_ * B_ * G4];      // xp + bias, [t][b][1024]
__device__ __align__(16) float g_states[(size_t)T_ * B_ * H_];  // masked h outputs [t][b][256]
__device__ __align__(16) float g_hA[H_ * B_];                   // h ping  [j][b]
__device__ __align__(16) float g_hB[H_ * B_];                   // h pong  [j][b]
__device__ unsigned char g_mask[T_ * B_];
__device__ unsigned g_bar[NBG];
__device__ float2 g_part[K1_BLOCKS];

// ------------------------- helpers ------------------------------------------
__device__ __forceinline__ ull pk2(float lo, float hi) {
    ull r; asm("mov.b64 %0, {%1, %2};" : "=l"(r) : "f"(lo), "f"(hi)); return r;
}
__device__ __forceinline__ void upk2(ull v, float& lo, float& hi) {
    asm("mov.b64 {%0, %1}, %2;" : "=f"(lo), "=f"(hi) : "l"(v));
}
__device__ __forceinline__ void fma2(ull& acc, ull a, ull b) {
    asm("fma.rn.f32x2 %0, %1, %2, %0;" : "+l"(acc) : "l"(a), "l"(b));
}
__device__ __forceinline__ ull add2(ull a, ull b) {
    ull r; asm("add.rn.f32x2 %0, %1, %2;" : "=l"(r) : "l"(a), "l"(b)); return r;
}
__device__ __forceinline__ float sig_(float x) {
    return __fdividef(1.f, 1.f + __expf(-x));
}
__device__ __forceinline__ float tanh_(float x) {
    float a = fabsf(x);
    float e = __expf(-2.f * a);
    float r = __fdividef(1.f - e, 1.f + e);
    return copysignf(r, x);
}

// ============================================================================
// K1: x_proj (+bias) -> g_xp, mask bytes, zero h0 + barrier counters.
// One warp per (b,t).
// ============================================================================
__global__ void k1_prep(const int* __restrict__ items, const int* __restrict__ actions,
                        const float* __restrict__ WihT, const float* __restrict__ b_lstm) {
    if (blockIdx.x == 0) {
        for (int i = threadIdx.x; i < H_ * B_ / 4; i += blockDim.x)
            ((float4*)g_hA)[i] = make_float4(0.f, 0.f, 0.f, 0.f);
        if (threadIdx.x < NBG) g_bar[threadIdx.x] = 0u;
    }
    int gw = blockIdx.x * 8 + (threadIdx.x >> 5);
    int lane = threadIdx.x & 31;
    if (gw >= T_ * B_) return;
    int b = gw & 63, t = gw >> 6;
    int it = items[b * S_ + t];
    int ac = actions[b * S_ + t];
    bool m = (it != 0);
    const float4* ra = (const float4*)(WihT + (size_t)it * G4);
    const float4* rb = (const float4*)(WihT + (size_t)(NI_ + ac) * G4);
    const float4* bi = (const float4*)b_lstm;
    float4* dst = (float4*)(g_xp + ((size_t)t * B_ + b) * G4);
#pragma unroll
    for (int p = 0; p < 8; p++) {
        int idx = lane + 32 * p;
        float4 bv = bi[idx];
        float4 o;
        if (m) {
            float4 a = ra[idx], c = rb[idx];
            o = make_float4(a.x + c.x + bv.x, a.y + c.y + bv.y,
                            a.z + c.z + bv.z, a.w + c.w + bv.w);
        } else {
            o = bv;
        }
        dst[idx] = o;
    }
    if (lane == 0) g_mask[t * B_ + b] = m ? 1 : 0;
}

// ============================================================================
// K2: persistent LSTM recurrence. 128 CTAs = 32 chunks x 4 batch groups.
// ============================================================================
__global__ void __launch_bounds__(256, 1)
k2_lstm(const float* __restrict__ Whh) {
    // h tile: row j uses 8 ull (16 floats) with pitch 10 ull (20 words) -> STS.128 conflict-free
    __shared__ __align__(16) ull smh[256 * 10];
    __shared__ __align__(16) ull smp[8 * 32 * 9];  // partials [w][col(pitch 9)][bp]
    __shared__ __align__(16) ull smg[256];         // gates [gate][e][bp]

    const int tid = threadIdx.x;
    const int cc = blockIdx.x & 31;   // column chunk
    const int bg = blockIdx.x >> 5;   // batch group

    const int w  = tid >> 5;          // compute: K-slice (warp)
    const int lc = tid & 31;          // compute: col in chunk (lane)
    const int col = tid >> 3;         // assembly: col in chunk
    const int bp  = tid & 7;          // assembly: batch pair

    // global Whh row for a chunk-local column x: (x&3)*256 + cc*8 + (x>>2)
    const int rowc = (lc & 3) * 256 + cc * 8 + (lc >> 2);
    const int rowa = (col & 3) * 256 + cc * 8 + (col >> 2);

    // weights packed {v,v} in registers: 32 x ull
    ull W2[32];
    {
        const float4* wr = (const float4*)(Whh + (size_t)rowc * H_ + w * 32);
#pragma unroll
        for (int p = 0; p < 8; p++) {
            float4 v = wr[p];
            W2[p * 4 + 0] = pk2(v.x, v.x);
            W2[p * 4 + 1] = pk2(v.y, v.y);
            W2[p * 4 + 2] = pk2(v.z, v.z);
            W2[p * 4 + 3] = pk2(v.w, v.w);
        }
    }

    const int b0 = bg * 16 + bp * 2;  // batch pair (even)
    float c0 = 0.f, c1 = 0.f, h0 = 0.f, h1 = 0.f;  // register-resident state (tid<64)

    volatile unsigned* bar = &g_bar[bg];

    for (int t = 0; t < T_; t++) {
        const float* rbuf = (t & 1) ? g_hB : g_hA;
        float* wbuf = (t & 1) ? g_hA : g_hB;

        // prefetch xp (all 256 threads map to (col,bp)) + mask
        float xa = g_xp[((size_t)t * B_ + b0) * G4 + rowa];
        float xb = g_xp[((size_t)t * B_ + b0 + 1) * G4 + rowa];
        unsigned char m0 = 0, m1 = 0;
        if (tid < 64) { m0 = g_mask[t * B_ + b0]; m1 = g_mask[t * B_ + b0 + 1]; }

        // stage h tile: rows j=0..255, this bg's 16 batches
        {
            int j = tid >> 2, q = tid & 3;
#pragma unroll
            for (int itr = 0; itr < 4; itr++) {
                int jj = j + itr * 64;
                float4 v = *(const float4*)(rbuf + jj * B_ + bg * 16 + q * 4);
                *(float4*)&smh[jj * 10 + q * 2] = v;
            }
        }
        __syncthreads();

        // partial dot products: acc[bp] += W[col][j] * h[j][2 batches]
        ull a0 = 0, a1 = 0, a2 = 0, a3 = 0, a4 = 0, a5 = 0, a6 = 0, a7 = 0;
        {
            const ull* hb = &smh[w * 32 * 10];
#pragma unroll
            for (int jj = 0; jj < 32; jj++) {
                ulonglong2 u01 = *(const ulonglong2*)&hb[jj * 10 + 0];
                ulonglong2 u23 = *(const ulonglong2*)&hb[jj * 10 + 2];
                ulonglong2 u45 = *(const ulonglong2*)&hb[jj * 10 + 4];
                ulonglong2 u67 = *(const ulonglong2*)&hb[jj * 10 + 6];
                fma2(a0, W2[jj], u01.x);
                fma2(a1, W2[jj], u01.y);
                fma2(a2, W2[jj], u23.x);
                fma2(a3, W2[jj], u23.y);
                fma2(a4, W2[jj], u45.x);
                fma2(a5, W2[jj], u45.y);
                fma2(a6, W2[jj], u67.x);
                fma2(a7, W2[jj], u67.y);
            }
        }
        {
            ull* p = &smp[(w * 32 + lc) * 9];
            p[0] = a0; p[1] = a1; p[2] = a2; p[3] = a3;
            p[4] = a4; p[5] = a5; p[6] = a6; p[7] = a7;
        }
        __syncthreads();

        // assemble gate value for (col, bp): sum 8 K-slices + xp
        {
            ull g = smp[col * 9 + bp];
#pragma unroll
            for (int ww = 1; ww < 8; ww++) g = add2(g, smp[(ww * 32 + col) * 9 + bp]);
            g = add2(g, pk2(xa, xb));
            smg[(col & 3) * 64 + (col >> 2) * 8 + bp] = g;
        }
        __syncthreads();

        // LSTM pointwise update: 64 threads own (e, batch-pair)
        if (tid < 64) {
            int e = tid >> 3;
            float i0, i1, f0, f1, gg0, gg1, o0, o1;
            upk2(smg[e * 8 + bp],        i0, i1);
            upk2(smg[64 + e * 8 + bp],   f0, f1);
            upk2(smg[128 + e * 8 + bp],  gg0, gg1);
            upk2(smg[192 + e * 8 + bp],  o0, o1);

            float out0, out1;
            {
                float ii = sig_(i0), ff = sig_(f0), gt = tanh_(gg0), oo = sig_(o0);
                float cn = ff * c0 + ii * gt;
                float hn = oo * tanh_(cn);
                if (m0) { c0 = cn; h0 = hn; out0 = hn; } else out0 = 0.f;
            }
            {
                float ii = sig_(i1), ff = sig_(f1), gt = tanh_(gg1), oo = sig_(o1);
                float cn = ff * c1 + ii * gt;
                float hn = oo * tanh_(cn);
                if (m1) { c1 = cn; h1 = hn; out1 = hn; } else out1 = 0.f;
            }
            int j = cc * 8 + e;
            *(ull*)(wbuf + j * B_ + b0) = pk2(h0, h1);   // publish h (post-mask)
            float* sp = g_states + ((size_t)t * B_ + b0) * H_ + j;
            sp[0]  = out0;
            sp[H_] = out1;
        }

        // per-batch-group barrier (32 CTAs), monotonic counter + release/acquire
        __syncthreads();
        if (tid == 0) {
            __threadfence();
            atomicAdd(&g_bar[bg], 1u);
            unsigned tgt = (unsigned)(t + 1) * NCC;
            while (*bar < tgt) { }
            __threadfence();
        }
        __syncthreads();
    }
}

// ============================================================================
// K3: query logits + per-(b,t) NLL; block partial sums (deterministic).
// One warp per (b,t): 1592 blocks x 8 warps = 12736 exactly.
// ============================================================================
__global__ void k3_loss(const int* __restrict__ items, const int* __restrict__ actions,
                        const float* __restrict__ temb, const float* __restrict__ Wq,
                        const float* __restrict__ bq) {
    __shared__ float2 sred[8];
    int gw = blockIdx.x * 8 + (threadIdx.x >> 5);
    int lane = threadIdx.x & 31;
    float nll = 0.f, cnt = 0.f;
    int b = gw & 63, t = gw >> 6;
    int qit = items[b * S_ + t + 1];
    if (qit != 0) {
        const float4* sv = (const float4*)(g_states + ((size_t)t * B_ + b) * H_);
        const float4* ev = (const float4*)(temb + (size_t)qit * H_);
        const float4* w0 = (const float4*)Wq;
        const float4* w1 = (const float4*)(Wq + H_);
        float d0 = 0.f, d1 = 0.f;
#pragma unroll
        for (int p = 0; p < 2; p++) {
            int idx = lane * 2 + p;
            float4 s = sv[idx], e = ev[idx], a = w0[idx], c = w1[idx];
            float es;
            es = e.x * s.x; d0 += es * a.x; d1 += es * c.x;
            es = e.y * s.y; d0 += es * a.y; d1 += es * c.y;
            es = e.z * s.z; d0 += es * a.z; d1 += es * c.z;
            es = e.w * s.w; d0 += es * a.w; d1 += es * c.w;
        }
        ull d = pk2(d0, d1);
#pragma unroll
        for (int off = 16; off; off >>= 1)
            d = add2(d, __shfl_xor_sync(0xffffffffu, d, off));
        upk2(d, d0, d1);
        if (lane == 0) {
            float q0 = d0 + bq[0], q1 = d1 + bq[1];
            int tgt = actions[b * S_ + t + 1];
            float mx = fmaxf(q0, q1), mn = fminf(q0, q1);
            float lse = mx + log1pf(__expf(mn - mx));
            nll = lse - (tgt ? q1 : q0);
            cnt = 1.f;
        }
    }
    if (lane == 0) sred[threadIdx.x >> 5] = make_float2(nll, cnt);
    __syncthreads();
    if (threadIdx.x == 0) {
        float s = 0.f, c = 0.f;
#pragma unroll
        for (int i = 0; i < 8; i++) { s += sred[i].x; c += sred[i].y; }
        g_part[blockIdx.x] = make_float2(s, c);
    }
}

// ============================================================================
// K4: final deterministic reduction -> loss
// ============================================================================
__global__ void k4_final(float* __restrict__ out) {
    __shared__ float ss[256], sc[256];
    float s = 0.f, c = 0.f;
    for (int i = threadIdx.x; i < K1_BLOCKS; i += 256) {
        float2 v = g_part[i];
        s += v.x; c += v.y;
    }
    ss[threadIdx.x] = s; sc[threadIdx.x] = c;
    __syncthreads();
    for (int st = 128; st; st >>= 1) {
        if (threadIdx.x < st) {
            ss[threadIdx.x] += ss[threadIdx.x + st];
            sc[threadIdx.x] += sc[threadIdx.x + st];
        }
        __syncthreads();
    }
    if (threadIdx.x == 0) out[0] = ss[0] / sc[0];
}

// ============================================================================
extern "C" void kernel_launch(void* const* d_in, const int* in_sizes, int n_in,
                              void* d_out, int out_size) {
    const int*   items   = (const int*)d_in[0];
    const int*   actions = (const int*)d_in[1];
    const float* WihT    = (const float*)d_in[2];
    const float* Whh     = (const float*)d_in[3];
    const float* b_lstm  = (const float*)d_in[4];
    const float* temb    = (const float*)d_in[5];
    const float* Wq      = (const float*)d_in[6];
    const float* bq      = (const float*)d_in[7];
    (void)in_sizes; (void)n_in; (void)out_size;

    k1_prep<<<K1_BLOCKS, 256>>>(items, actions, WihT, b_lstm);
    k2_lstm<<<NCC * NBG, 256>>>(Whh);
    k3_loss<<<K1_BLOCKS, 256>>>(items, actions, temb, Wq, bq);
    k4_final<<<1, 256>>>((float*)d_out);
}

// round 4
// speedup vs baseline: 1.1131x; 1.1131x over previous
#include <cuda_runtime.h>
#include <cuda_bf16.h>
#include <cstdint>
#include <cstddef>

typedef unsigned long long ull;

#define B_  64
#define S_  200
#define T_  199
#define H_  256
#define G4  1024
#define NI_ 50000

#define NCC 32          // column chunks: each owns 8 h-elems x 4 gates = 32 gate rows
#define NBG 4           // independent batch groups of 16
#define K1_BLOCKS 1592  // 1592*8 warps = 199*64 (b,t) pairs exactly

// ------------------------- device scratch (no allocs allowed) ---------------
__device__ __align__(16) float g_xp[(size_t)T_ * B_ * G4];      // xp + bias, [t][b][1024]
__device__ __align__(16) float g_states[(size_t)T_ * B_ * H_];  // masked h outputs [t][b][256]
__device__ __align__(16) float g_hA[H_ * B_];                   // h ping  [j][b]
__device__ __align__(16) float g_hB[H_ * B_];                   // h pong  [j][b]
__device__ unsigned char g_mask[T_ * B_];
__device__ unsigned g_bar[NBG];
__device__ unsigned g_k3done;
__device__ float2 g_part[K1_BLOCKS];

// ------------------------- helpers ------------------------------------------
__device__ __forceinline__ ull pk2(float lo, float hi) {
    ull r; asm("mov.b64 %0, {%1, %2};" : "=l"(r) : "f"(lo), "f"(hi)); return r;
}
__device__ __forceinline__ void upk2(ull v, float& lo, float& hi) {
    asm("mov.b64 {%0, %1}, %2;" : "=f"(lo), "=f"(hi) : "l"(v));
}
__device__ __forceinline__ void fma2(ull& acc, ull a, ull b) {
    asm("fma.rn.f32x2 %0, %1, %2, %0;" : "+l"(acc) : "l"(a), "l"(b));
}
__device__ __forceinline__ ull add2(ull a, ull b) {
    ull r; asm("add.rn.f32x2 %0, %1, %2;" : "=l"(r) : "l"(a), "l"(b)); return r;
}
__device__ __forceinline__ float sig_(float x) {
    return __fdividef(1.f, 1.f + __expf(-x));
}
__device__ __forceinline__ float tanh_(float x) {
    float a = fabsf(x);
    float e = __expf(-2.f * a);
    float r = __fdividef(1.f - e, 1.f + e);
    return copysignf(r, x);
}
__device__ __forceinline__ float4 ldcv4(const float* p) {
    float4 v;
    asm volatile("ld.global.cv.v4.f32 {%0,%1,%2,%3}, [%4];"
                 : "=f"(v.x), "=f"(v.y), "=f"(v.z), "=f"(v.w) : "l"(p));
    return v;
}
__device__ __forceinline__ void red_release_add(unsigned* p) {
    asm volatile("red.release.gpu.global.add.u32 [%0], %1;" :: "l"(p), "r"(1u) : "memory");
}
__device__ __forceinline__ unsigned ld_acquire(const unsigned* p) {
    unsigned v;
    asm volatile("ld.acquire.gpu.global.u32 %0, [%1];" : "=r"(v) : "l"(p) : "memory");
    return v;
}

// ============================================================================
// K1: x_proj (+bias) -> g_xp, mask bytes, zero h0 + barrier/flag resets.
// One warp per (b,t).
// ============================================================================
__global__ void k1_prep(const int* __restrict__ items, const int* __restrict__ actions,
                        const float* __restrict__ WihT, const float* __restrict__ b_lstm) {
    if (blockIdx.x == 0) {
        for (int i = threadIdx.x; i < H_ * B_ / 4; i += blockDim.x)
            ((float4*)g_hA)[i] = make_float4(0.f, 0.f, 0.f, 0.f);
        if (threadIdx.x < NBG) g_bar[threadIdx.x] = 0u;
        if (threadIdx.x == NBG) g_k3done = 0u;
    }
    int gw = blockIdx.x * 8 + (threadIdx.x >> 5);
    int lane = threadIdx.x & 31;
    if (gw >= T_ * B_) return;
    int b = gw & 63, t = gw >> 6;
    int it = items[b * S_ + t];
    int ac = actions[b * S_ + t];
    bool m = (it != 0);
    const float4* ra = (const float4*)(WihT + (size_t)it * G4);
    const float4* rb = (const float4*)(WihT + (size_t)(NI_ + ac) * G4);
    const float4* bi = (const float4*)b_lstm;
    float4* dst = (float4*)(g_xp + ((size_t)t * B_ + b) * G4);
#pragma unroll
    for (int p = 0; p < 8; p++) {
        int idx = lane + 32 * p;
        float4 bv = bi[idx];
        float4 o;
        if (m) {
            float4 a = ra[idx], c = rb[idx];
            o = make_float4(a.x + c.x + bv.x, a.y + c.y + bv.y,
                            a.z + c.z + bv.z, a.w + c.w + bv.w);
        } else {
            o = bv;
        }
        dst[idx] = o;
    }
    if (lane == 0) g_mask[t * B_ + b] = m ? 1 : 0;
}

// ============================================================================
// K2: persistent LSTM recurrence. 128 CTAs = 32 chunks x 4 batch groups.
// Release/acquire barrier (no MEMBAR.GPU), cv h-loads, shfl gate gather.
// ============================================================================
__global__ void __launch_bounds__(256, 1)
k2_lstm(const float* __restrict__ Whh) {
    // h tile: row j uses 8 ull (16 floats) with pitch 10 ull -> STS.128 conflict-free
    __shared__ __align__(16) ull smh[256 * 10];
    __shared__ __align__(16) ull smp[8 * 32 * 9];  // partials [w][col(pitch 9)][bp]

    const int tid = threadIdx.x;
    const int cc = blockIdx.x & 31;   // column chunk
    const int bg = blockIdx.x >> 5;   // batch group

    const int w  = tid >> 5;          // compute: K-slice = warp; assembly: e = warp
    const int lc = tid & 31;          // compute: col in chunk (lane)
    const int lane = lc;
    const int gate = (tid >> 3) & 3;  // assembly: gate (lane>>3)
    const int bp   = tid & 7;         // assembly: batch pair (lane&7)
    const int colq = w * 4 + gate;    // assembly: chunk-local col for (e=w, gate)

    // global Whh row for a chunk-local column x (x&3=gate, x>>2=e):
    const int rowc = (lc & 3) * 256 + cc * 8 + (lc >> 2);   // compute col
    const int rowa = gate * 256 + cc * 8 + w;               // assembly col

    // weights packed {v,v} in registers: 32 x ull
    ull W2[32];
    {
        const float4* wr = (const float4*)(Whh + (size_t)rowc * H_ + w * 32);
#pragma unroll
        for (int p = 0; p < 8; p++) {
            float4 v = wr[p];
            W2[p * 4 + 0] = pk2(v.x, v.x);
            W2[p * 4 + 1] = pk2(v.y, v.y);
            W2[p * 4 + 2] = pk2(v.z, v.z);
            W2[p * 4 + 3] = pk2(v.w, v.w);
        }
    }

    const int b0 = bg * 16 + bp * 2;             // batch pair (even)
    float c0 = 0.f, c1 = 0.f, h0 = 0.f, h1 = 0.f; // state lives on lanes<8 of each warp

    unsigned* bar = &g_bar[bg];

    // xp/mask prefetch pointers & regs (t = 0)
    const float* xptr = g_xp + (size_t)b0 * G4 + rowa;
    const unsigned char* mptr = g_mask + b0;
    float xa = xptr[0], xb = xptr[G4];
    uchar2 mv = make_uchar2(0, 0);
    if (lane < 8) mv = *(const uchar2*)mptr;

    for (int t = 0; t < T_; t++) {
        const float* rbuf = (t & 1) ? g_hB : g_hA;
        float* wbuf = (t & 1) ? g_hA : g_hB;

        // stage h tile (L1-bypassing cv loads: always-fresh from L2)
        {
            int j = tid >> 2, q = tid & 3;
#pragma unroll
            for (int itr = 0; itr < 4; itr++) {
                int jj = j + itr * 64;
                float4 v = ldcv4(rbuf + jj * B_ + bg * 16 + q * 4);
                *(float4*)&smh[jj * 10 + q * 2] = v;
            }
        }
        __syncthreads();

        // partial dot products: acc[bp] += W[col][j] * h[j][2 batches]
        ull a0 = 0, a1 = 0, a2 = 0, a3 = 0, a4 = 0, a5 = 0, a6 = 0, a7 = 0;
        {
            const ull* hb = &smh[w * 32 * 10];
#pragma unroll
            for (int jj = 0; jj < 32; jj++) {
                ulonglong2 u01 = *(const ulonglong2*)&hb[jj * 10 + 0];
                ulonglong2 u23 = *(const ulonglong2*)&hb[jj * 10 + 2];
                ulonglong2 u45 = *(const ulonglong2*)&hb[jj * 10 + 4];
                ulonglong2 u67 = *(const ulonglong2*)&hb[jj * 10 + 6];
                fma2(a0, W2[jj], u01.x);
                fma2(a1, W2[jj], u01.y);
                fma2(a2, W2[jj], u23.x);
                fma2(a3, W2[jj], u23.y);
                fma2(a4, W2[jj], u45.x);
                fma2(a5, W2[jj], u45.y);
                fma2(a6, W2[jj], u67.x);
                fma2(a7, W2[jj], u67.y);
            }
        }
        {
            ull* p = &smp[(w * 32 + lc) * 9];
            p[0] = a0; p[1] = a1; p[2] = a2; p[3] = a3;
            p[4] = a4; p[5] = a5; p[6] = a6; p[7] = a7;
        }

        // prefetch xp/mask for t+1 (overlaps reduce + barrier)
        float nxa = xa, nxb = xb;
        uchar2 nmv = mv;
        if (t + 1 < T_) {
            nxa = xptr[(size_t)(t + 1) * B_ * G4];
            nxb = xptr[(size_t)(t + 1) * B_ * G4 + G4];
            if (lane < 8) nmv = *(const uchar2*)(mptr + (t + 1) * B_);
        }
        __syncthreads();

        // assemble gate value for (colq, bp): sum 8 K-slices + xp
        ull g = smp[colq * 9 + bp];
#pragma unroll
        for (int ww = 1; ww < 8; ww++) g = add2(g, smp[(ww * 32 + colq) * 9 + bp]);
        g = add2(g, pk2(xa, xb));

        // gather i,f,g,o for (e=w, bp) into lanes<8 via shuffles
        ull vf = __shfl_sync(0xffffffffu, g, (lane & 7) + 8);
        ull vg = __shfl_sync(0xffffffffu, g, (lane & 7) + 16);
        ull vo = __shfl_sync(0xffffffffu, g, (lane & 7) + 24);

        if (lane < 8) {
            float i0, i1, f0, f1, gg0, gg1, o0, o1;
            upk2(g,  i0, i1);
            upk2(vf, f0, f1);
            upk2(vg, gg0, gg1);
            upk2(vo, o0, o1);

            float out0, out1;
            {
                float ii = sig_(i0), ff = sig_(f0), gt = tanh_(gg0), oo = sig_(o0);
                float cn = ff * c0 + ii * gt;
                float hn = oo * tanh_(cn);
                if (mv.x) { c0 = cn; h0 = hn; out0 = hn; } else out0 = 0.f;
            }
            {
                float ii = sig_(i1), ff = sig_(f1), gt = tanh_(gg1), oo = sig_(o1);
                float cn = ff * c1 + ii * gt;
                float hn = oo * tanh_(cn);
                if (mv.y) { c1 = cn; h1 = hn; out1 = hn; } else out1 = 0.f;
            }
            int j = cc * 8 + w;
            *(ull*)(wbuf + j * B_ + b0) = pk2(h0, h1);   // publish h (post-mask)
            float* sp = g_states + ((size_t)t * B_ + b0) * H_ + j;
            sp[0]  = out0;
            sp[H_] = out1;
        }
        xa = nxa; xb = nxb; mv = nmv;

        // per-batch-group barrier: CTA sync -> release add -> acquire poll
        __syncthreads();
        if (tid == 0) {
            red_release_add(bar);
            unsigned tgt = (unsigned)(t + 1) * NCC;
            while (ld_acquire(bar) < tgt) { }
        }
        __syncthreads();
    }
}

// ============================================================================
// K3: query logits + per-(b,t) NLL; block partials + fused deterministic
// last-block final reduction. One warp per (b,t): 1592 blocks x 8 warps.
// ============================================================================
__global__ void k3_loss(const int* __restrict__ items, const int* __restrict__ actions,
                        const float* __restrict__ temb, const float* __restrict__ Wq,
                        const float* __restrict__ bq, float* __restrict__ out) {
    __shared__ float2 sred[8];
    __shared__ unsigned slast;
    int gw = blockIdx.x * 8 + (threadIdx.x >> 5);
    int lane = threadIdx.x & 31;
    float nll = 0.f, cnt = 0.f;
    int b = gw & 63, t = gw >> 6;
    int qit = items[b * S_ + t + 1];
    if (qit != 0) {
        const float4* sv = (const float4*)(g_states + ((size_t)t * B_ + b) * H_);
        const float4* ev = (const float4*)(temb + (size_t)qit * H_);
        const float4* w0 = (const float4*)Wq;
        const float4* w1 = (const float4*)(Wq + H_);
        float d0 = 0.f, d1 = 0.f;
#pragma unroll
        for (int p = 0; p < 2; p++) {
            int idx = lane * 2 + p;
            float4 s = sv[idx], e = ev[idx], a = w0[idx], c = w1[idx];
            float es;
            es = e.x * s.x; d0 += es * a.x; d1 += es * c.x;
            es = e.y * s.y; d0 += es * a.y; d1 += es * c.y;
            es = e.z * s.z; d0 += es * a.z; d1 += es * c.z;
            es = e.w * s.w; d0 += es * a.w; d1 += es * c.w;
        }
        ull d = pk2(d0, d1);
#pragma unroll
        for (int off = 16; off; off >>= 1)
            d = add2(d, __shfl_xor_sync(0xffffffffu, d, off));
        upk2(d, d0, d1);
        if (lane == 0) {
            float q0 = d0 + bq[0], q1 = d1 + bq[1];
            int tgt = actions[b * S_ + t + 1];
            float mx = fmaxf(q0, q1), mn = fminf(q0, q1);
            float lse = mx + log1pf(__expf(mn - mx));
            nll = lse - (tgt ? q1 : q0);
            cnt = 1.f;
        }
    }
    if (lane == 0) sred[threadIdx.x >> 5] = make_float2(nll, cnt);
    __syncthreads();
    if (threadIdx.x == 0) {
        float s = 0.f, c = 0.f;
#pragma unroll
        for (int i = 0; i < 8; i++) { s += sred[i].x; c += sred[i].y; }
        g_part[blockIdx.x] = make_float2(s, c);
        __threadfence();
        unsigned o = atomicAdd(&g_k3done, 1u);
        slast = (o == K1_BLOCKS - 1) ? 1u : 0u;
    }
    __syncthreads();
    if (slast) {
        // deterministic final reduction: fixed order regardless of which block runs it
        __shared__ float ss[256], sc[256];
        __threadfence();
        float s = 0.f, c = 0.f;
        for (int i = threadIdx.x; i < K1_BLOCKS; i += 256) {
            float2 v = g_part[i];
            s += v.x; c += v.y;
        }
        ss[threadIdx.x] = s; sc[threadIdx.x] = c;
        __syncthreads();
        for (int st = 128; st; st >>= 1) {
            if (threadIdx.x < st) {
                ss[threadIdx.x] += ss[threadIdx.x + st];
                sc[threadIdx.x] += sc[threadIdx.x + st];
            }
            __syncthreads();
        }
        if (threadIdx.x == 0) out[0] = ss[0] / sc[0];
    }
}

// ============================================================================
extern "C" void kernel_launch(void* const* d_in, const int* in_sizes, int n_in,
                              void* d_out, int out_size) {
    const int*   items   = (const int*)d_in[0];
    const int*   actions = (const int*)d_in[1];
    const float* WihT    = (const float*)d_in[2];
    const float* Whh     = (const float*)d_in[3];
    const float* b_lstm  = (const float*)d_in[4];
    const float* temb    = (const float*)d_in[5];
    const float* Wq      = (const float*)d_in[6];
    const float* bq      = (const float*)d_in[7];
    (void)in_sizes; (void)n_in; (void)out_size;

    k1_prep<<<K1_BLOCKS, 256>>>(items, actions, WihT, b_lstm);
    k2_lstm<<<NCC * NBG, 256>>>(Whh);
    k3_loss<<<K1_BLOCKS, 256>>>(items, actions, temb, Wq, bq, (float*)d_out);
}